// round 1
// baseline (speedup 1.0000x reference)
#include <cuda_runtime.h>

// out[b,i,j,c1,c2,k]: k=0 -> x[b,i,c1,c2], k=1 -> x[b,j,c1,c2]
// B=64, GS=96, C=8. Output floats = 64*96*96*64*2 = 75,497,472.
// One float4 per thread: (xi[c], xj[c], xi[c+1], xj[c+1]).
// 32 float4 per (b,i,j) tile == one warp per tile -> coalesced 512B store bursts.

static constexpr int GS = 96;
static constexpr int C  = 8;
static constexpr int ROW = C * C;                 // 64 floats per (b,g) block
static constexpr int V4_PER_TILE = ROW * 2 / 4;   // 32 float4 per (b,i,j)

__global__ void __launch_bounds__(256)
combo_kernel(const float* __restrict__ x, float4* __restrict__ out, int total_v4)
{
    int v = blockIdx.x * blockDim.x + threadIdx.x;
    if (v >= total_v4) return;

    int t    = v & (V4_PER_TILE - 1);   // 0..31 within tile
    int tile = v >> 5;                  // (b,i,j) tile index

    int j  = tile % GS;
    int bi = tile / GS;
    int i  = bi % GS;
    int b  = bi / GS;

    int off = t * 2;                    // float offset within the 64-float block

    const float2* xi = reinterpret_cast<const float2*>(x + (b * GS + i) * ROW + off);
    const float2* xj = reinterpret_cast<const float2*>(x + (b * GS + j) * ROW + off);

    float2 a = __ldg(xi);
    float2 c = __ldg(xj);

    out[v] = make_float4(a.x, c.x, a.y, c.y);
}

extern "C" void kernel_launch(void* const* d_in, const int* in_sizes, int n_in,
                              void* d_out, int out_size)
{
    const float* x = (const float*)d_in[0];
    float4* out = (float4*)d_out;

    int total_v4 = out_size / 4;  // 18,874,368
    int threads = 256;
    int blocks = (total_v4 + threads - 1) / threads;

    combo_kernel<<<blocks, threads>>>(x, out, total_v4);
}

// round 4
// speedup vs baseline: 1.2562x; 1.2562x over previous
#include <cuda_runtime.h>

// out[b,i,j,c1,c2,k]: k=0 -> x[b,i,c1,c2], k=1 -> x[b,j,c1,c2]
// B=64, GS=96, C=8. Tile (b,i,j) = 128 floats, interleaved (xi[e], xj[e]).
//
// Block = one (b,i): xi float4 hoisted into registers, loop over 96 j's.
// 16 threads per tile, 32 B (float8) per thread via st.global.v8.f32
// (sm_100+ 256-bit store) -> 1 LDG.128 + 1 STG.256 per 1024 B of output
// per warp, lifting the LSU-issue ceiling above the HBM write ceiling.

static constexpr int GS = 96;
static constexpr int ROW = 64;  // 8*8 floats per (b,g) block

__global__ void __launch_bounds__(256)
combo_kernel(const float* __restrict__ x, float* __restrict__ out)
{
    const int bi = blockIdx.x;            // b*GS + i
    const int t = threadIdx.x;
    const int lane16 = t & 15;            // element-group within tile
    const int jbase  = t >> 4;            // 0..15

    // xi: this thread's 4 elements of x[b,i], loop-invariant
    const float4 a = *reinterpret_cast<const float4*>(x + bi * ROW + lane16 * 4);

    const float* xb = x + (bi / GS) * GS * ROW;          // x[b, 0]
    float* outb = out + (size_t)bi * GS * 128;           // out[b, i, 0]

#pragma unroll
    for (int it = 0; it < GS / 16; ++it) {
        const int j = jbase + it * 16;
        const float4 c =
            *reinterpret_cast<const float4*>(xb + j * ROW + lane16 * 4);
        float* p = outb + j * 128 + lane16 * 8;
        asm volatile(
            "st.global.v8.f32 [%0], {%1,%2,%3,%4,%5,%6,%7,%8};" ::
            "l"(p),
            "f"(a.x), "f"(c.x), "f"(a.y), "f"(c.y),
            "f"(a.z), "f"(c.z), "f"(a.w), "f"(c.w)
            : "memory");
    }
}

extern "C" void kernel_launch(void* const* d_in, const int* in_sizes, int n_in,
                              void* d_out, int out_size)
{
    const float* x = (const float*)d_in[0];
    float* out = (float*)d_out;

    // one block per (b, i): 64*96 = 6144 blocks
    combo_kernel<<<64 * GS, 256>>>(x, out);
}

// round 6
// speedup vs baseline: 1.2698x; 1.0108x over previous
#include <cuda_runtime.h>

// out[b,i,j,c1,c2,k]: k=0 -> x[b,i,c1,c2], k=1 -> x[b,j,c1,c2]
// B=64, GS=96, C=8. Tile (b,i,j) = 128 floats, interleaved (xi[e], xj[e]).
//
// Block = one (b,i). xi float4 hoisted to registers. All 6 xj loads issued
// up-front (MLP=6), then 6 STG.256 back-to-back with no scoreboard waits.
// Streaming (.cs) stores: output passes L2 exactly once, evict-first.

static constexpr int GS = 96;
static constexpr int ROW = 64;  // 8*8 floats per (b,g) block

__global__ void __launch_bounds__(256)
combo_kernel(const float* __restrict__ x, float* __restrict__ out)
{
    const int bi = blockIdx.x;            // b*GS + i
    const int t = threadIdx.x;
    const int lane16 = t & 15;            // element-group within tile
    const int jbase  = t >> 4;            // 0..15

    // xi: this thread's 4 elements of x[b,i], loop-invariant
    const float4 a = *reinterpret_cast<const float4*>(x + bi * ROW + lane16 * 4);

    const float* xb = x + (bi / GS) * GS * ROW;          // x[b, 0]
    float* outb = out + (size_t)bi * GS * 128;           // out[b, i, 0]

    // Preload all 6 xj vectors (independent loads, MLP=6)
    float4 c[6];
#pragma unroll
    for (int it = 0; it < 6; ++it) {
        const int j = jbase + it * 16;
        c[it] = *reinterpret_cast<const float4*>(xb + j * ROW + lane16 * 4);
    }

    // 6 back-to-back 256-bit streaming stores
#pragma unroll
    for (int it = 0; it < 6; ++it) {
        const int j = jbase + it * 16;
        float* p = outb + j * 128 + lane16 * 8;
        asm volatile(
            "st.global.cs.v8.f32 [%0], {%1,%2,%3,%4,%5,%6,%7,%8};" ::
            "l"(p),
            "f"(a.x), "f"(c[it].x), "f"(a.y), "f"(c[it].y),
            "f"(a.z), "f"(c[it].z), "f"(a.w), "f"(c[it].w)
            : "memory");
    }
}

extern "C" void kernel_launch(void* const* d_in, const int* in_sizes, int n_in,
                              void* d_out, int out_size)
{
    const float* x = (const float*)d_in[0];
    float* out = (float*)d_out;

    // one block per (b, i): 64*96 = 6144 blocks
    combo_kernel<<<64 * GS, 256>>>(x, out);
}